// round 7
// baseline (speedup 1.0000x reference)
#include <cuda_runtime.h>
#include <cuda_bf16.h>
#include <math.h>

// Problem constants
#define BATCH   64
#define NF      256
#define WIN     128
#define EMB     128
#define TOPK    32
#define ALPHA   0.2f

// Packed fp32x2 ops (sm_100+; ptxas never auto-fuses these from C++)
#define FMA2(d, a, b, c) \
    asm("fma.rn.f32x2 %0, %1, %2, %3;" : "=l"(d) : "l"(a), "l"(b), "l"(c))
#define PACK2(d, lo, hi) \
    asm("mov.b64 %0, {%1, %2};" : "=l"(d) : "f"(lo), "f"(hi))
#define UNPACK2(lo, hi, s) \
    asm("mov.b64 {%0, %1}, %2;" : "=f"(lo), "=f"(hi) : "l"(s))

// Scratch
__device__ float g_Wx[BATCH * NF * EMB];   // Wx = x_n @ W_n + b_n  (8.4 MB)
__device__ float g_d1[BATCH * NF];         // dot(Wx[b,r], a[:128])
__device__ float g_d2[BATCH * NF];         // dot(Wx[b,r], a[128:])

__device__ __forceinline__ float lrelu(float v) {
    return fmaxf(v, ALPHA * v);   // valid for alpha in (0,1)
}

// ---------------------------------------------------------------------------
// Kernel 1: GEMM  Wx[r][e] = sum_w x[r][w]*W[w][e] + b[e], fused d1/d2.
// 128 blocks x (128M x 128N) tile, 256 thr, 8x8 microtile with packed
// fma.rn.f32x2 accumulators (2 FMA/instr -> halves the FFMA issue floor).
// Thread (tx,ty): m = ty*8..+7, e = tx*8..+7. acc2[i2][j] = {acc[2i2][j], acc[2i2+1][j]}.
// ---------------------------------------------------------------------------
__global__ __launch_bounds__(256, 2) void gemm_wx_kernel(
    const float* __restrict__ x,   // [BATCH*NF, WIN]
    const float* __restrict__ Wn,  // [WIN, EMB]
    const float* __restrict__ bn,  // [EMB]
    const float* __restrict__ a)   // [2*EMB]
{
    __shared__ float sX[32][132];   // [k][m], 132 pad keeps float4 alignment
    __shared__ float sW[32][132];   // [k][e]

    const int t    = threadIdx.x;
    const int row0 = blockIdx.x * 128;
    const int tx   = t & 15;        // e-tile
    const int ty   = t >> 4;        // m-tile

    unsigned long long acc2[4][8];
#pragma unroll
    for (int i = 0; i < 4; i++)
#pragma unroll
        for (int j = 0; j < 8; j++) acc2[i][j] = 0ull;

    for (int kt = 0; kt < WIN; kt += 32) {
        // X tile: 128 rows x 32 k, transposed into sX[k][m]
#pragma unroll
        for (int i = 0; i < 16; i++) {
            int idx = t + i * 256;
            int m = idx >> 5, w = idx & 31;
            sX[w][m] = x[(size_t)(row0 + m) * WIN + kt + w];
        }
        // W tile: 32 k x 128 e
#pragma unroll
        for (int i = 0; i < 16; i++) {
            int idx = t + i * 256;
            int kk = idx >> 7, e = idx & 127;
            sW[kk][e] = Wn[(size_t)(kt + kk) * EMB + e];
        }
        __syncthreads();

#pragma unroll
        for (int kk = 0; kk < 32; kk++) {
            float4 xa = *(const float4*)&sX[kk][ty * 8];
            float4 xb = *(const float4*)&sX[kk][ty * 8 + 4];
            float4 wa = *(const float4*)&sW[kk][tx * 8];
            float4 wb = *(const float4*)&sW[kk][tx * 8 + 4];

            unsigned long long ra2[4], rb2[8];
            PACK2(ra2[0], xa.x, xa.y);
            PACK2(ra2[1], xa.z, xa.w);
            PACK2(ra2[2], xb.x, xb.y);
            PACK2(ra2[3], xb.z, xb.w);
            PACK2(rb2[0], wa.x, wa.x);
            PACK2(rb2[1], wa.y, wa.y);
            PACK2(rb2[2], wa.z, wa.z);
            PACK2(rb2[3], wa.w, wa.w);
            PACK2(rb2[4], wb.x, wb.x);
            PACK2(rb2[5], wb.y, wb.y);
            PACK2(rb2[6], wb.z, wb.z);
            PACK2(rb2[7], wb.w, wb.w);

#pragma unroll
            for (int i2 = 0; i2 < 4; i2++)
#pragma unroll
                for (int j = 0; j < 8; j++)
                    FMA2(acc2[i2][j], ra2[i2], rb2[j], acc2[i2][j]);
        }
        __syncthreads();
    }

    // Unpack accumulators
    float acc[8][8];
#pragma unroll
    for (int i2 = 0; i2 < 4; i2++)
#pragma unroll
        for (int j = 0; j < 8; j++)
            UNPACK2(acc[2 * i2][j], acc[2 * i2 + 1][j], acc2[i2][j]);

    // Epilogue: bias, store Wx, fused projections d1/d2
    float a1v[8], a2v[8], bnv[8];
#pragma unroll
    for (int j = 0; j < 8; j++) {
        int e = tx * 8 + j;
        a1v[j] = __ldg(a + e);
        a2v[j] = __ldg(a + EMB + e);
        bnv[j] = __ldg(bn + e);
    }
    float p1[8], p2[8];
#pragma unroll
    for (int i = 0; i < 8; i++) { p1[i] = 0.0f; p2[i] = 0.0f; }

#pragma unroll
    for (int i = 0; i < 8; i++) {
        int m = row0 + ty * 8 + i;
        float v[8];
#pragma unroll
        for (int j = 0; j < 8; j++) {
            v[j] = acc[i][j] + bnv[j];
            p1[i] = fmaf(v[j], a1v[j], p1[i]);
            p2[i] = fmaf(v[j], a2v[j], p2[i]);
        }
        float4* dst = (float4*)(g_Wx + (size_t)m * EMB + tx * 8);
        dst[0] = make_float4(v[0], v[1], v[2], v[3]);
        dst[1] = make_float4(v[4], v[5], v[6], v[7]);
    }
    // Reduce across the 16 tx lanes (lanes 0-15 / 16-31 share ty)
#pragma unroll
    for (int i = 0; i < 8; i++) {
#pragma unroll
        for (int o = 8; o > 0; o >>= 1) {
            p1[i] += __shfl_xor_sync(0xffffffffu, p1[i], o);
            p2[i] += __shfl_xor_sync(0xffffffffu, p2[i], o);
        }
    }
    if (tx == 0) {
#pragma unroll
        for (int i = 0; i < 8; i++) {
            int m = row0 + ty * 8 + i;
            g_d1[m] = p1[i];
            g_d2[m] = p2[i];
        }
    }
}

// ---------------------------------------------------------------------------
// Kernel 2: batch-affine attention + streaming output (round-6 WIN, kept).
// 128 blocks x 1024 threads, block = half-batch; batch's Wx slice (128 KB)
// stays L1-resident so gathers are L1 hits, off the LTS path.
// ---------------------------------------------------------------------------
__global__ __launch_bounds__(1024) void attn_stream_kernel(
    const int*   __restrict__ edge,   // [2, NF*TOPK] (row 0 used)
    const float* __restrict__ bias,   // [NF, TOPK]
    float*       __restrict__ out)    // [BATCH, NF, TOPK, EMB]
{
    const int t    = threadIdx.x;
    const int w    = t >> 5;          // warp 0..31
    const int l    = t & 31;
    const int b    = blockIdx.x >> 1;         // batch
    const int half = blockIdx.x & 1;          // which 128 n's

    const float* d1  = g_d1 + b * NF;
    const float* d2  = g_d2 + b * NF;
    const float* wxb = g_Wx + (size_t)b * NF * EMB;

#pragma unroll 1
    for (int r = 0; r < 4; r++) {
        const int n  = half * 128 + r * 32 + w;
        const int gw = b * NF + n;

        const int nbr_l = __ldg(edge + n * TOPK + l);

        float score;
        if (l < 16) {
            score = lrelu(d1[n] + d2[n]);
        } else {
            int j0 = 2 * l - 32;
            int n0 = __ldg(edge + n * TOPK + j0);
            int n1 = __ldg(edge + n * TOPK + j0 + 1);
            score = lrelu(d1[n0] + d2[n1]);
        }
        float bv = __ldg(bias + n * TOPK + l);
        if (isnan(bv)) bv = 0.0f;
        else if (isinf(bv)) bv = bv > 0.0f ? 3.4028235e38f : -3.4028235e38f;
        score += bv;

        // Warp softmax over 32 lanes
        float m = score;
#pragma unroll
        for (int o = 16; o > 0; o >>= 1) m = fmaxf(m, __shfl_xor_sync(0xffffffffu, m, o));
        float ex = __expf(score - m);
        float s = ex;
#pragma unroll
        for (int o = 16; o > 0; o >>= 1) s += __shfl_xor_sync(0xffffffffu, s, o);
        const float att = ex / s;

        // Streaming output: 32 rows x 32 float4
        float4* outp = (float4*)(out + (size_t)gw * TOPK * EMB);

#pragma unroll 8
        for (int k = 0; k < TOPK; k++) {
            int   nb = __shfl_sync(0xffffffffu, nbr_l, k);
            float ak = __shfl_sync(0xffffffffu, att,   k);
            const float4* src = (const float4*)(wxb + (size_t)nb * EMB);
            float4 v = __ldg(src + l);
            v.x = lrelu(v.x) * ak;
            v.y = lrelu(v.y) * ak;
            v.z = lrelu(v.z) * ak;
            v.w = lrelu(v.w) * ak;
            __stcs(outp + k * 32 + l, v);
        }
    }
}

// ---------------------------------------------------------------------------
// Launch. Inputs: 0:x_n 1:x_e 2:edge_indices 3:all_embeddings 4:W_n 5:b_n
//                 6:a 7:bias_n   (x_e, all_embeddings unused)
// ---------------------------------------------------------------------------
extern "C" void kernel_launch(void* const* d_in, const int* in_sizes, int n_in,
                              void* d_out, int out_size) {
    const float* x_n  = (const float*)d_in[0];
    const int*   edge = (const int*)  d_in[2];
    const float* W_n  = (const float*)d_in[4];
    const float* b_n  = (const float*)d_in[5];
    const float* a    = (const float*)d_in[6];
    const float* bias = (const float*)d_in[7];
    float* out = (float*)d_out;

    gemm_wx_kernel<<<(BATCH * NF) / 128, 256>>>(x_n, W_n, b_n, a);
    attn_stream_kernel<<<BATCH * 2, 1024>>>(edge, bias, out);
}

// round 13
// speedup vs baseline: 1.1491x; 1.1491x over previous
#include <cuda_runtime.h>
#include <cuda_bf16.h>
#include <math.h>

// Problem constants
#define BATCH   64
#define NF      256
#define WIN     128
#define EMB     128
#define TOPK    32
#define ALPHA   0.2f

// Scratch
__device__ float         g_Wx[BATCH * NF * EMB];   // Wx = x@W + b (8.4 MB)
__device__ float         g_d1[BATCH * NF];         // dot(Wx[b,r], a[:128])
__device__ float         g_d2[BATCH * NF];         // dot(Wx[b,r], a[128:])
__device__ __nv_bfloat16 g_WhT[EMB * WIN];         // hi(W)^T  [e][w]
__device__ __nv_bfloat16 g_WlT[EMB * WIN];         // lo(W)^T  [e][w]

__device__ __forceinline__ float lrelu(float v) {
    return fmaxf(v, ALPHA * v);
}

// ---------------------------------------------------------------------------
// Kernel 0: split W into bf16 hi/lo, transposed to [e][w]. 16384 elems.
// ---------------------------------------------------------------------------
__global__ __launch_bounds__(256) void prep_w_kernel(const float* __restrict__ Wn) {
    int idx = blockIdx.x * 256 + threadIdx.x;   // 0..16383
    int w = idx >> 7, e = idx & 127;
    float v = __ldg(Wn + idx);
    __nv_bfloat16 hi = __float2bfloat16(v);
    __nv_bfloat16 lo = __float2bfloat16(v - __bfloat162float(hi));
    g_WhT[e * WIN + w] = hi;
    g_WlT[e * WIN + w] = lo;
}

// ===========================================================================
// Tensor-core GEMM via mma.sync (bf16, fp32 accum), 2-term input split.
// ===========================================================================
#define P_BF 136          // bf16 smem pitch (272 B: 16B-aligned, conflict-free LDSM)
#define P_F  132          // float smem pitch for C staging

// smem byte offsets
#define S_AH  0
#define S_AL  (S_AH + 128 * P_BF * 2)       //  34816
#define S_BH  (S_AL + 128 * P_BF * 2)       //  69632
#define S_BL  (S_BH + 128 * P_BF * 2)       // 104448
#define S_VEC (S_BL + 128 * P_BF * 2)       // 139264: bn | a1 | a2
#define GEMM_SMEM (S_VEC + 3 * 128 * 4)     // 140800 bytes
// C staging reuses [S_AH, S_AH + 128*P_F*4) = 67584 B (< S_BH)

__device__ __forceinline__ unsigned smem_u32(const void* p) {
    unsigned a;
    asm("{ .reg .u64 t; cvta.to.shared.u64 t, %1; cvt.u32.u64 %0, t; }"
        : "=r"(a) : "l"(p));
    return a;
}
#define LDSM_X4(r0, r1, r2, r3, addr) \
    asm volatile("ldmatrix.sync.aligned.m8n8.x4.shared.b16 {%0,%1,%2,%3}, [%4];" \
                 : "=r"(r0), "=r"(r1), "=r"(r2), "=r"(r3) : "r"(addr))
#define MMA_BF16(c, a, b) \
    asm volatile("mma.sync.aligned.m16n8k16.row.col.f32.bf16.bf16.f32 " \
                 "{%0,%1,%2,%3}, {%4,%5,%6,%7}, {%8,%9}, {%0,%1,%2,%3};" \
                 : "+f"((c)[0]), "+f"((c)[1]), "+f"((c)[2]), "+f"((c)[3]) \
                 : "r"((a)[0]), "r"((a)[1]), "r"((a)[2]), "r"((a)[3]), \
                   "r"((b)[0]), "r"((b)[1]))

// ---------------------------------------------------------------------------
// Kernel 1: GEMM Wx = x@W + b with fused d1/d2. 128 CTAs x 256 thr.
// Per CTA: 128 rows x 128 cols x K=128. Warp grid 4(m) x 2(n): warp tile 32x64.
// Groups: Ah*Bh + Al*Bh + Ah*Bl  (Al*Bl dropped, ~2^-18).
// ---------------------------------------------------------------------------
__global__ __launch_bounds__(256) void gemm_mma_kernel(
    const float* __restrict__ x,   // [BATCH*NF, WIN]
    const float* __restrict__ bn,  // [EMB]
    const float* __restrict__ a)   // [2*EMB]
{
    extern __shared__ char smem[];
    const unsigned sb = smem_u32(smem);
    const int t   = threadIdx.x;
    const int l   = t & 31;
    const int wid = t >> 5;
    const int wm  = wid & 3;       // m-warp: rows wm*32..+31
    const int wn  = wid >> 2;      // n-warp: cols wn*64..+63
    const int row0 = blockIdx.x * 128;

    // Small vectors
    if (t < 128) {
        ((float*)(smem + S_VEC))[t]       = __ldg(bn + t);
        ((float*)(smem + S_VEC))[128 + t] = __ldg(a + t);
        ((float*)(smem + S_VEC))[256 + t] = __ldg(a + EMB + t);
    }

    // A tiles: x rows -> bf16 hi/lo, padded [row][col], pitch P_BF
#pragma unroll
    for (int i = 0; i < 16; i++) {
        int idx4 = t + i * 256;                 // 0..4095 float4s
        int row  = idx4 >> 5;
        int c4   = (idx4 & 31) << 2;
        float4 v = __ldg((const float4*)(x + (size_t)(row0 + row) * WIN) + (idx4 & 31));
        float f[4] = {v.x, v.y, v.z, v.w};
        __nv_bfloat16 h[4], lo[4];
#pragma unroll
        for (int j = 0; j < 4; j++) {
            h[j]  = __float2bfloat16(f[j]);
            lo[j] = __float2bfloat16(f[j] - __bfloat162float(h[j]));
        }
        unsigned off = (unsigned)(row * P_BF + c4) * 2u;
        *(__nv_bfloat162*)(smem + S_AH + off)     = __nv_bfloat162(h[0], h[1]);
        *(__nv_bfloat162*)(smem + S_AH + off + 4) = __nv_bfloat162(h[2], h[3]);
        *(__nv_bfloat162*)(smem + S_AL + off)     = __nv_bfloat162(lo[0], lo[1]);
        *(__nv_bfloat162*)(smem + S_AL + off + 4) = __nv_bfloat162(lo[2], lo[3]);
    }

    // B tiles: pre-split W^T [e][w] bf16, copied 8 bf16 (16B) at a time
#pragma unroll
    for (int i = 0; i < 8; i++) {
        int idx8 = t + i * 256;                 // 0..2047 uint4s
        int row  = idx8 >> 4;                   // e
        int c8   = (idx8 & 15) << 3;            // w chunk
        uint4 vh = __ldg((const uint4*)(g_WhT + row * WIN + c8));
        uint4 vl = __ldg((const uint4*)(g_WlT + row * WIN + c8));
        unsigned off = (unsigned)(row * P_BF + c8) * 2u;
        *(uint4*)(smem + S_BH + off) = vh;
        *(uint4*)(smem + S_BL + off) = vl;
    }
    __syncthreads();

    // Accumulators: c[mi][nj][4]
    float c[2][8][4];
#pragma unroll
    for (int mi = 0; mi < 2; mi++)
#pragma unroll
        for (int nj = 0; nj < 8; nj++)
#pragma unroll
            for (int q = 0; q < 4; q++) c[mi][nj][q] = 0.0f;

    // A frag address: row = wm*32 + mi*16 + (l&15), col = 16s + (l>>4)*8
    // B frag address (x4 = two n8-tiles): row = base + (l>>4)*8 + (l&7),
    //                                     col = 16s + ((l>>3)&1)*8
    const unsigned aRow = (unsigned)(wm * 32 + (l & 15));
    const unsigned aColSel = (unsigned)((l >> 4) * 8);
    const unsigned bRowSel = (unsigned)(((l >> 4) & 1) * 8 + (l & 7));
    const unsigned bColSel = (unsigned)(((l >> 3) & 1) * 8);

#pragma unroll
    for (int s = 0; s < 8; s++) {
        unsigned aoff = ((aRow * P_BF) + 16u * s + aColSel) * 2u;
        unsigned aH[2][4], aL[2][4];
        LDSM_X4(aH[0][0], aH[0][1], aH[0][2], aH[0][3], sb + S_AH + aoff);
        LDSM_X4(aH[1][0], aH[1][1], aH[1][2], aH[1][3], sb + S_AH + aoff + 16u * P_BF * 2u);
        LDSM_X4(aL[0][0], aL[0][1], aL[0][2], aL[0][3], sb + S_AL + aoff);
        LDSM_X4(aL[1][0], aL[1][1], aL[1][2], aL[1][3], sb + S_AL + aoff + 16u * P_BF * 2u);

        unsigned bH[8][2], bL[8][2];
#pragma unroll
        for (int j = 0; j < 4; j++) {
            unsigned brow = (unsigned)(wn * 64 + j * 16) + bRowSel;
            unsigned boff = (brow * P_BF + 16u * s + bColSel) * 2u;
            LDSM_X4(bH[2*j][0], bH[2*j][1], bH[2*j+1][0], bH[2*j+1][1], sb + S_BH + boff);
            LDSM_X4(bL[2*j][0], bL[2*j][1], bL[2*j+1][0], bL[2*j+1][1], sb + S_BL + boff);
        }

#pragma unroll
        for (int mi = 0; mi < 2; mi++)
#pragma unroll
            for (int nj = 0; nj < 8; nj++) {
                MMA_BF16(c[mi][nj], aH[mi], bH[nj]);
                MMA_BF16(c[mi][nj], aL[mi], bH[nj]);
                MMA_BF16(c[mi][nj], aH[mi], bL[nj]);
            }
    }

    // Stage C to smem (reuse A region), then coalesced epilogue
    __syncthreads();
    float* sC = (float*)(smem + S_AH);
#pragma unroll
    for (int mi = 0; mi < 2; mi++) {
        int r0 = wm * 32 + mi * 16 + (l >> 2);
#pragma unroll
        for (int nj = 0; nj < 8; nj++) {
            int c0 = wn * 64 + nj * 8 + (l & 3) * 2;
            sC[r0 * P_F + c0]           = c[mi][nj][0];
            sC[r0 * P_F + c0 + 1]       = c[mi][nj][1];
            sC[(r0 + 8) * P_F + c0]     = c[mi][nj][2];
            sC[(r0 + 8) * P_F + c0 + 1] = c[mi][nj][3];
        }
    }
    __syncthreads();

    // Pass 2: thread t -> row t>>1, cols (t&1)*64..+63. Bias + d1/d2 + store.
    {
        const float* s_bn = (const float*)(smem + S_VEC);
        const float* s_a1 = s_bn + 128;
        const float* s_a2 = s_bn + 256;
        int row  = t >> 1;
        int half = t & 1;
        int cb   = half * 64;
        float p1 = 0.0f, p2 = 0.0f;
        float4* dst = (float4*)(g_Wx + (size_t)(row0 + row) * EMB + cb);
#pragma unroll
        for (int c4 = 0; c4 < 64; c4 += 4) {
            int cc = cb + c4;
            float v0 = sC[row * P_F + cc]     + s_bn[cc];
            float v1 = sC[row * P_F + cc + 1] + s_bn[cc + 1];
            float v2 = sC[row * P_F + cc + 2] + s_bn[cc + 2];
            float v3 = sC[row * P_F + cc + 3] + s_bn[cc + 3];
            p1 = fmaf(v0, s_a1[cc], p1);     p2 = fmaf(v0, s_a2[cc], p2);
            p1 = fmaf(v1, s_a1[cc + 1], p1); p2 = fmaf(v1, s_a2[cc + 1], p2);
            p1 = fmaf(v2, s_a1[cc + 2], p1); p2 = fmaf(v2, s_a2[cc + 2], p2);
            p1 = fmaf(v3, s_a1[cc + 3], p1); p2 = fmaf(v3, s_a2[cc + 3], p2);
            dst[c4 >> 2] = make_float4(v0, v1, v2, v3);
        }
        // Partner thread t^1 (adjacent lane) holds the other 64 cols
        p1 += __shfl_xor_sync(0xffffffffu, p1, 1);
        p2 += __shfl_xor_sync(0xffffffffu, p2, 1);
        if (half == 0) {
            g_d1[row0 + row] = p1;
            g_d2[row0 + row] = p2;
        }
    }
}

// ---------------------------------------------------------------------------
// Kernel 2: batch-affine attention + streaming output (round-6 WIN, kept).
// ---------------------------------------------------------------------------
__global__ __launch_bounds__(1024) void attn_stream_kernel(
    const int*   __restrict__ edge,   // [2, NF*TOPK] (row 0 used)
    const float* __restrict__ bias,   // [NF, TOPK]
    float*       __restrict__ out)    // [BATCH, NF, TOPK, EMB]
{
    const int t    = threadIdx.x;
    const int w    = t >> 5;
    const int l    = t & 31;
    const int b    = blockIdx.x >> 1;
    const int half = blockIdx.x & 1;

    const float* d1  = g_d1 + b * NF;
    const float* d2  = g_d2 + b * NF;
    const float* wxb = g_Wx + (size_t)b * NF * EMB;

#pragma unroll 1
    for (int r = 0; r < 4; r++) {
        const int n  = half * 128 + r * 32 + w;
        const int gw = b * NF + n;

        const int nbr_l = __ldg(edge + n * TOPK + l);

        float score;
        if (l < 16) {
            score = lrelu(d1[n] + d2[n]);
        } else {
            int j0 = 2 * l - 32;
            int n0 = __ldg(edge + n * TOPK + j0);
            int n1 = __ldg(edge + n * TOPK + j0 + 1);
            score = lrelu(d1[n0] + d2[n1]);
        }
        float bv = __ldg(bias + n * TOPK + l);
        if (isnan(bv)) bv = 0.0f;
        else if (isinf(bv)) bv = bv > 0.0f ? 3.4028235e38f : -3.4028235e38f;
        score += bv;

        float m = score;
#pragma unroll
        for (int o = 16; o > 0; o >>= 1) m = fmaxf(m, __shfl_xor_sync(0xffffffffu, m, o));
        float ex = __expf(score - m);
        float s = ex;
#pragma unroll
        for (int o = 16; o > 0; o >>= 1) s += __shfl_xor_sync(0xffffffffu, s, o);
        const float att = ex / s;

        float4* outp = (float4*)(out + (size_t)gw * TOPK * EMB);

#pragma unroll 8
        for (int k = 0; k < TOPK; k++) {
            int   nb = __shfl_sync(0xffffffffu, nbr_l, k);
            float ak = __shfl_sync(0xffffffffu, att,   k);
            const float4* src = (const float4*)(wxb + (size_t)nb * EMB);
            float4 v = __ldg(src + l);
            v.x = lrelu(v.x) * ak;
            v.y = lrelu(v.y) * ak;
            v.z = lrelu(v.z) * ak;
            v.w = lrelu(v.w) * ak;
            __stcs(outp + k * 32 + l, v);
        }
    }
}

// ---------------------------------------------------------------------------
// Launch. Inputs: 0:x_n 1:x_e 2:edge_indices 3:all_embeddings 4:W_n 5:b_n
//                 6:a 7:bias_n   (x_e, all_embeddings unused)
// ---------------------------------------------------------------------------
extern "C" void kernel_launch(void* const* d_in, const int* in_sizes, int n_in,
                              void* d_out, int out_size) {
    const float* x_n  = (const float*)d_in[0];
    const int*   edge = (const int*)  d_in[2];
    const float* W_n  = (const float*)d_in[4];
    const float* b_n  = (const float*)d_in[5];
    const float* a    = (const float*)d_in[6];
    const float* bias = (const float*)d_in[7];
    float* out = (float*)d_out;

    prep_w_kernel<<<64, 256>>>(W_n);
    cudaFuncSetAttribute(gemm_mma_kernel,
                         cudaFuncAttributeMaxDynamicSharedMemorySize, GEMM_SMEM);
    gemm_mma_kernel<<<(BATCH * NF) / 128, 256, GEMM_SMEM>>>(x_n, b_n, a);
    attn_stream_kernel<<<BATCH * 2, 1024>>>(edge, bias, out);
}

// round 14
// speedup vs baseline: 1.1503x; 1.0011x over previous
#include <cuda_runtime.h>
#include <cuda_bf16.h>
#include <math.h>

// Problem constants
#define BATCH   64
#define NF      256
#define WIN     128
#define EMB     128
#define TOPK    32
#define ALPHA   0.2f

// Scratch
__device__ float g_Wx[BATCH * NF * EMB];   // Wx = x@W + b (8.4 MB)
__device__ float g_d1[BATCH * NF];         // dot(Wx[b,r], a[:128])
__device__ float g_d2[BATCH * NF];         // dot(Wx[b,r], a[128:])

__device__ __forceinline__ float lrelu(float v) {
    return fmaxf(v, ALPHA * v);
}

// ===========================================================================
// Tensor-core GEMM via mma.sync (bf16, fp32 accum), 2-term input split.
// ===========================================================================
#define P_BF 136          // bf16 smem pitch (272 B: 16B-aligned, conflict-free LDSM)
#define P_F  132          // float smem pitch for C staging

// smem byte offsets
#define S_AH  0
#define S_AL  (S_AH + 128 * P_BF * 2)       //  34816
#define S_BH  (S_AL + 128 * P_BF * 2)       //  69632
#define S_BL  (S_BH + 128 * P_BF * 2)       // 104448
#define S_VEC (S_BL + 128 * P_BF * 2)       // 139264: bn | a1 | a2
#define GEMM_SMEM (S_VEC + 3 * 128 * 4)     // 140800 bytes
// C staging reuses [S_AH, S_AH + 128*P_F*4) = 67584 B (< S_BH)

__device__ __forceinline__ unsigned smem_u32(const void* p) {
    unsigned a;
    asm("{ .reg .u64 t; cvta.to.shared.u64 t, %1; cvt.u32.u64 %0, t; }"
        : "=r"(a) : "l"(p));
    return a;
}
#define LDSM_X4(r0, r1, r2, r3, addr) \
    asm volatile("ldmatrix.sync.aligned.m8n8.x4.shared.b16 {%0,%1,%2,%3}, [%4];" \
                 : "=r"(r0), "=r"(r1), "=r"(r2), "=r"(r3) : "r"(addr))
#define MMA_BF16(c, a, b) \
    asm volatile("mma.sync.aligned.m16n8k16.row.col.f32.bf16.bf16.f32 " \
                 "{%0,%1,%2,%3}, {%4,%5,%6,%7}, {%8,%9}, {%0,%1,%2,%3};" \
                 : "+f"((c)[0]), "+f"((c)[1]), "+f"((c)[2]), "+f"((c)[3]) \
                 : "r"((a)[0]), "r"((a)[1]), "r"((a)[2]), "r"((a)[3]), \
                   "r"((b)[0]), "r"((b)[1]))

// ---------------------------------------------------------------------------
// Kernel 1: GEMM Wx = x@W + b with fused d1/d2. 128 CTAs x 256 thr.
// Per CTA: 128 rows x 128 cols x K=128. Warp grid 4(m) x 2(n): warp tile 32x64.
// W is split into bf16 hi/lo IN-KERNEL (no prep launch; L2-hit after CTA 0).
// Groups: Ah*Bh + Al*Bh + Ah*Bl  (Al*Bl dropped, ~2^-18).
// ---------------------------------------------------------------------------
__global__ __launch_bounds__(256) void gemm_mma_kernel(
    const float* __restrict__ x,   // [BATCH*NF, WIN]
    const float* __restrict__ Wn,  // [WIN, EMB]
    const float* __restrict__ bn,  // [EMB]
    const float* __restrict__ a)   // [2*EMB]
{
    extern __shared__ char smem[];
    const unsigned sb = smem_u32(smem);
    const int t   = threadIdx.x;
    const int l   = t & 31;
    const int wid = t >> 5;
    const int wm  = wid & 3;       // m-warp: rows wm*32..+31
    const int wn  = wid >> 2;      // n-warp: cols wn*64..+63
    const int row0 = blockIdx.x * 128;

    // Small vectors
    if (t < 128) {
        ((float*)(smem + S_VEC))[t]       = __ldg(bn + t);
        ((float*)(smem + S_VEC))[128 + t] = __ldg(a + t);
        ((float*)(smem + S_VEC))[256 + t] = __ldg(a + EMB + t);
    }

    // B tiles: load W fp32 [w][e] coalesced, split hi/lo, store transposed
    // sB[e][w] (bf16, pitch P_BF). L2-hit after the first CTA.
#pragma unroll
    for (int i = 0; i < 64; i++) {
        int idx = t + i * 256;                  // 0..16383
        int w = idx >> 7, e = idx & 127;
        float v = __ldg(Wn + idx);
        __nv_bfloat16 hi = __float2bfloat16(v);
        __nv_bfloat16 lo = __float2bfloat16(v - __bfloat162float(hi));
        unsigned off = (unsigned)(e * P_BF + w) * 2u;
        *(__nv_bfloat16*)(smem + S_BH + off) = hi;
        *(__nv_bfloat16*)(smem + S_BL + off) = lo;
    }

    // A tiles: x rows -> bf16 hi/lo, padded [row][col], pitch P_BF
#pragma unroll
    for (int i = 0; i < 16; i++) {
        int idx4 = t + i * 256;                 // 0..4095 float4s
        int row  = idx4 >> 5;
        int c4   = (idx4 & 31) << 2;
        float4 v = __ldg((const float4*)(x + (size_t)(row0 + row) * WIN) + (idx4 & 31));
        float f[4] = {v.x, v.y, v.z, v.w};
        __nv_bfloat16 h[4], lo[4];
#pragma unroll
        for (int j = 0; j < 4; j++) {
            h[j]  = __float2bfloat16(f[j]);
            lo[j] = __float2bfloat16(f[j] - __bfloat162float(h[j]));
        }
        unsigned off = (unsigned)(row * P_BF + c4) * 2u;
        *(__nv_bfloat162*)(smem + S_AH + off)     = __nv_bfloat162(h[0], h[1]);
        *(__nv_bfloat162*)(smem + S_AH + off + 4) = __nv_bfloat162(h[2], h[3]);
        *(__nv_bfloat162*)(smem + S_AL + off)     = __nv_bfloat162(lo[0], lo[1]);
        *(__nv_bfloat162*)(smem + S_AL + off + 4) = __nv_bfloat162(lo[2], lo[3]);
    }
    __syncthreads();

    // Accumulators: c[mi][nj][4]
    float c[2][8][4];
#pragma unroll
    for (int mi = 0; mi < 2; mi++)
#pragma unroll
        for (int nj = 0; nj < 8; nj++)
#pragma unroll
            for (int q = 0; q < 4; q++) c[mi][nj][q] = 0.0f;

    // A frag: row = wm*32 + mi*16 + (l&15), col = 16s + (l>>4)*8
    // B frag (x4 = two n8-tiles): row = base + (l>>4)*8 + (l&7),
    //                             col = 16s + ((l>>3)&1)*8
    const unsigned aRow    = (unsigned)(wm * 32 + (l & 15));
    const unsigned aColSel = (unsigned)((l >> 4) * 8);
    const unsigned bRowSel = (unsigned)(((l >> 4) & 1) * 8 + (l & 7));
    const unsigned bColSel = (unsigned)(((l >> 3) & 1) * 8);

#pragma unroll
    for (int s = 0; s < 8; s++) {
        unsigned aoff = ((aRow * P_BF) + 16u * s + aColSel) * 2u;
        unsigned aH[2][4], aL[2][4];
        LDSM_X4(aH[0][0], aH[0][1], aH[0][2], aH[0][3], sb + S_AH + aoff);
        LDSM_X4(aH[1][0], aH[1][1], aH[1][2], aH[1][3], sb + S_AH + aoff + 16u * P_BF * 2u);
        LDSM_X4(aL[0][0], aL[0][1], aL[0][2], aL[0][3], sb + S_AL + aoff);
        LDSM_X4(aL[1][0], aL[1][1], aL[1][2], aL[1][3], sb + S_AL + aoff + 16u * P_BF * 2u);

        unsigned bH[8][2], bL[8][2];
#pragma unroll
        for (int j = 0; j < 4; j++) {
            unsigned brow = (unsigned)(wn * 64 + j * 16) + bRowSel;
            unsigned boff = (brow * P_BF + 16u * s + bColSel) * 2u;
            LDSM_X4(bH[2*j][0], bH[2*j][1], bH[2*j+1][0], bH[2*j+1][1], sb + S_BH + boff);
            LDSM_X4(bL[2*j][0], bL[2*j][1], bL[2*j+1][0], bL[2*j+1][1], sb + S_BL + boff);
        }

#pragma unroll
        for (int mi = 0; mi < 2; mi++)
#pragma unroll
            for (int nj = 0; nj < 8; nj++) {
                MMA_BF16(c[mi][nj], aH[mi], bH[nj]);
                MMA_BF16(c[mi][nj], aL[mi], bH[nj]);
                MMA_BF16(c[mi][nj], aH[mi], bL[nj]);
            }
    }

    // Stage C to smem (reuse A region), then coalesced epilogue
    __syncthreads();
    float* sC = (float*)(smem + S_AH);
#pragma unroll
    for (int mi = 0; mi < 2; mi++) {
        int r0 = wm * 32 + mi * 16 + (l >> 2);
#pragma unroll
        for (int nj = 0; nj < 8; nj++) {
            int c0 = wn * 64 + nj * 8 + (l & 3) * 2;
            sC[r0 * P_F + c0]           = c[mi][nj][0];
            sC[r0 * P_F + c0 + 1]       = c[mi][nj][1];
            sC[(r0 + 8) * P_F + c0]     = c[mi][nj][2];
            sC[(r0 + 8) * P_F + c0 + 1] = c[mi][nj][3];
        }
    }
    __syncthreads();

    // Pass 2: thread t -> row t>>1, cols (t&1)*64..+63. Bias + d1/d2 + store.
    {
        const float* s_bn = (const float*)(smem + S_VEC);
        const float* s_a1 = s_bn + 128;
        const float* s_a2 = s_bn + 256;
        int row  = t >> 1;
        int half = t & 1;
        int cb   = half * 64;
        float p1 = 0.0f, p2 = 0.0f;
        float4* dst = (float4*)(g_Wx + (size_t)(row0 + row) * EMB + cb);
#pragma unroll
        for (int c4 = 0; c4 < 64; c4 += 4) {
            int cc = cb + c4;
            float v0 = sC[row * P_F + cc]     + s_bn[cc];
            float v1 = sC[row * P_F + cc + 1] + s_bn[cc + 1];
            float v2 = sC[row * P_F + cc + 2] + s_bn[cc + 2];
            float v3 = sC[row * P_F + cc + 3] + s_bn[cc + 3];
            p1 = fmaf(v0, s_a1[cc], p1);     p2 = fmaf(v0, s_a2[cc], p2);
            p1 = fmaf(v1, s_a1[cc + 1], p1); p2 = fmaf(v1, s_a2[cc + 1], p2);
            p1 = fmaf(v2, s_a1[cc + 2], p1); p2 = fmaf(v2, s_a2[cc + 2], p2);
            p1 = fmaf(v3, s_a1[cc + 3], p1); p2 = fmaf(v3, s_a2[cc + 3], p2);
            dst[c4 >> 2] = make_float4(v0, v1, v2, v3);
        }
        // Partner thread t^1 (adjacent lane) holds the other 64 cols
        p1 += __shfl_xor_sync(0xffffffffu, p1, 1);
        p2 += __shfl_xor_sync(0xffffffffu, p2, 1);
        if (half == 0) {
            g_d1[row0 + row] = p1;
            g_d2[row0 + row] = p2;
        }
    }
}

// ---------------------------------------------------------------------------
// Kernel 2: batch-affine attention + streaming output (round-6 WIN).
// 128 blocks x 1024 threads, block = half-batch; batch's Wx slice (128 KB)
// stays L1-resident so gathers are L1 hits, off the LTS path.
// Score-phase neighbor indices come from shuffles (lane 2l-32's nbr_l),
// not extra LDGs.
// ---------------------------------------------------------------------------
__global__ __launch_bounds__(1024) void attn_stream_kernel(
    const int*   __restrict__ edge,   // [2, NF*TOPK] (row 0 used)
    const float* __restrict__ bias,   // [NF, TOPK]
    float*       __restrict__ out)    // [BATCH, NF, TOPK, EMB]
{
    const int t    = threadIdx.x;
    const int w    = t >> 5;
    const int l    = t & 31;
    const int b    = blockIdx.x >> 1;
    const int half = blockIdx.x & 1;

    const float* d1  = g_d1 + b * NF;
    const float* d2  = g_d2 + b * NF;
    const float* wxb = g_Wx + (size_t)b * NF * EMB;

#pragma unroll 1
    for (int r = 0; r < 4; r++) {
        const int n  = half * 128 + r * 32 + w;
        const int gw = b * NF + n;

        const int nbr_l = __ldg(edge + n * TOPK + l);

        // Score: neighbor indices for lane l>=16 are lanes (2l-32), (2l-31)
        int j0 = (2 * l - 32) & 31;
        int n0 = __shfl_sync(0xffffffffu, nbr_l, j0);
        int n1 = __shfl_sync(0xffffffffu, nbr_l, j0 + 1);
        float score;
        if (l < 16) score = lrelu(d1[n] + d2[n]);
        else        score = lrelu(d1[n0] + d2[n1]);

        float bv = __ldg(bias + n * TOPK + l);
        if (isnan(bv)) bv = 0.0f;
        else if (isinf(bv)) bv = bv > 0.0f ? 3.4028235e38f : -3.4028235e38f;
        score += bv;

        float m = score;
#pragma unroll
        for (int o = 16; o > 0; o >>= 1) m = fmaxf(m, __shfl_xor_sync(0xffffffffu, m, o));
        float ex = __expf(score - m);
        float s = ex;
#pragma unroll
        for (int o = 16; o > 0; o >>= 1) s += __shfl_xor_sync(0xffffffffu, s, o);
        const float att = ex / s;

        float4* outp = (float4*)(out + (size_t)gw * TOPK * EMB);

#pragma unroll 8
        for (int k = 0; k < TOPK; k++) {
            int   nb = __shfl_sync(0xffffffffu, nbr_l, k);
            float ak = __shfl_sync(0xffffffffu, att,   k);
            const float4* src = (const float4*)(wxb + (size_t)nb * EMB);
            float4 v = __ldg(src + l);
            v.x = lrelu(v.x) * ak;
            v.y = lrelu(v.y) * ak;
            v.z = lrelu(v.z) * ak;
            v.w = lrelu(v.w) * ak;
            __stcs(outp + k * 32 + l, v);
        }
    }
}

// ---------------------------------------------------------------------------
// Launch. Inputs: 0:x_n 1:x_e 2:edge_indices 3:all_embeddings 4:W_n 5:b_n
//                 6:a 7:bias_n   (x_e, all_embeddings unused)
// ---------------------------------------------------------------------------
extern "C" void kernel_launch(void* const* d_in, const int* in_sizes, int n_in,
                              void* d_out, int out_size) {
    const float* x_n  = (const float*)d_in[0];
    const int*   edge = (const int*)  d_in[2];
    const float* W_n  = (const float*)d_in[4];
    const float* b_n  = (const float*)d_in[5];
    const float* a    = (const float*)d_in[6];
    const float* bias = (const float*)d_in[7];
    float* out = (float*)d_out;

    cudaFuncSetAttribute(gemm_mma_kernel,
                         cudaFuncAttributeMaxDynamicSharedMemorySize, GEMM_SMEM);
    gemm_mma_kernel<<<(BATCH * NF) / 128, 256, GEMM_SMEM>>>(x_n, W_n, b_n, a);
    attn_stream_kernel<<<BATCH * 2, 1024>>>(edge, bias, out);
}